// round 2
// baseline (speedup 1.0000x reference)
#include <cuda_runtime.h>
#include <stdint.h>

#define BN 8
#define HN 480
#define WN 640
#define GN 368640
#define TOTAL (BN*GN)
#define NPIX (BN*HN*WN)

#define U0c 320.0f
#define V0c 240.0f
#define DCOS 0.867f
#define DXY 0.01f

// ---------------- device scratch (no allocations allowed) ----------------
static __device__ float2       g_zip[NPIX];          // (gt, pred) per pixel
static __device__ unsigned int g_keys[TOTAL];        // L bits (masked) or 0xFFFFFFFF
static __device__ unsigned int g_hist_hi[65536];
static __device__ unsigned int g_hist_lo[65536];
static __device__ double       g_total_sum;
static __device__ double       g_sum_below;
static __device__ unsigned int g_n;
static __device__ unsigned int g_bucket;
static __device__ unsigned int g_rrem;

// ---------------- K0: zero scratch (graph replays reuse globals) ----------
__global__ void k_zero() {
    int i = blockIdx.x * blockDim.x + threadIdx.x;
    if (i < 65536) { g_hist_hi[i] = 0u; g_hist_lo[i] = 0u; }
    if (i == 0) {
        g_total_sum = 0.0; g_sum_below = 0.0;
        g_n = 0u; g_bucket = 0u; g_rrem = 0u;
    }
}

// ---------------- Kz: interleave gt/pred so gathers hit one sector -------
__global__ void k_zip(const float* __restrict__ gt, const float* __restrict__ pr) {
    int i = blockIdx.x * blockDim.x + threadIdx.x;
    if (i >= NPIX / 4) return;
    float4 a = __ldg(&((const float4*)gt)[i]);
    float4 b = __ldg(&((const float4*)pr)[i]);
    float2* o = &g_zip[i * 4];
    o[0] = make_float2(a.x, b.x);
    o[1] = make_float2(a.y, b.y);
    o[2] = make_float2(a.z, b.z);
    o[3] = make_float2(a.w, b.w);
}

// ---------------- K1: main compute -------------------------------------
__global__ void k_main(const int* __restrict__ p1x, const int* __restrict__ p1y,
                       const int* __restrict__ p2x, const int* __restrict__ p2y,
                       const int* __restrict__ p3x, const int* __restrict__ p3y) {
    int g = blockIdx.x * blockDim.x + threadIdx.x;
    if (g >= GN) return;

    int x1 = p1x[g], y1 = p1y[g];
    int x2 = p2x[g], y2 = p2y[g];
    int x3 = p3x[g], y3 = p3y[g];
    int pix1 = y1 * WN + x1, pix2 = y2 * WN + x2, pix3 = y3 * WN + x3;
    float u1 = (float)x1 - U0c, vv1 = (float)y1 - V0c;
    float u2 = (float)x2 - U0c, vv2 = (float)y2 - V0c;
    float u3 = (float)x3 - U0c, vv3 = (float)y3 - V0c;
    const float rfx = 1.0f / 519.0f, rfy = 1.0f / 519.0f;

    double lsum = 0.0;
    unsigned int lcnt = 0;

    #pragma unroll 1
    for (int b = 0; b < BN; b++) {
        const float2* zb = &g_zip[b * HN * WN];
        float2 z1 = __ldg(&zb[pix1]);
        float2 z2 = __ldg(&zb[pix2]);
        float2 z3 = __ldg(&zb[pix3]);

        // --- gt point cloud points ---
        float a1 = fabsf(z1.x), a2 = fabsf(z2.x), a3 = fabsf(z3.x);
        float P1x = u1 * a1 * rfx, P1y = vv1 * a1 * rfy, P1z = z1.x;
        float P2x = u2 * a2 * rfx, P2y = vv2 * a2 * rfy, P2z = z2.x;
        float P3x = u3 * a3 * rfx, P3y = vv3 * a3 * rfy, P3z = z3.x;

        // D vectors: d12, d13, d23
        float v0x = P2x - P1x, v0y = P2y - P1y, v0z = P2z - P1z;
        float w1x = P3x - P1x, w1y = P3y - P1y, w1z = P3z - P1z;
        float w2x = P3x - P2x, w2y = P3y - P2y, w2z = P3z - P2z;

        float e00 = v0x*v0x + v0y*v0y + v0z*v0z;
        float e11 = w1x*w1x + w1y*w1y + w1z*w1z;
        float e22 = w2x*w2x + w2y*w2y + w2z*w2z;
        float e01 = v0x*w1x + v0y*w1y + v0z*w1z;
        float e02 = v0x*w2x + v0y*w2y + v0z*w2z;
        float e12 = w1x*w2x + w1y*w2y + w1z*w2z;
        float n0 = sqrtf(e00), n1 = sqrtf(e11), n2 = sqrtf(e22);

        int cnt = 0;
        cnt += (fabsf(e00 / (n0*n0 + 1e-8f)) > DCOS);
        cnt += (fabsf(e11 / (n1*n1 + 1e-8f)) > DCOS);
        cnt += (fabsf(e22 / (n2*n2 + 1e-8f)) > DCOS);
        cnt += 2 * (fabsf(e01 / (n0*n1 + 1e-8f)) > DCOS);
        cnt += 2 * (fabsf(e02 / (n0*n2 + 1e-8f)) > DCOS);
        cnt += 2 * (fabsf(e12 / (n1*n2 + 1e-8f)) > DCOS);
        bool mask_cos = cnt > 3;

        bool mx = (fabsf(v0x) < DXY) | (fabsf(w1x) < DXY) | (fabsf(w2x) < DXY);
        bool my = (fabsf(v0y) < DXY) | (fabsf(w1y) < DXY) | (fabsf(w2y) < DXY);
        bool mz = (fabsf(v0z) < DXY) | (fabsf(w1z) < DXY) | (fabsf(w2z) < DXY);
        bool maskf = !((mx && my && mz) || mask_cos);

        // --- pred point cloud points ---
        float b1 = fabsf(z1.y), b2 = fabsf(z2.y), b3 = fabsf(z3.y);
        float Q1x = u1 * b1 * rfx, Q1y = vv1 * b1 * rfy, Q1z = z1.y;
        float Q2x = u2 * b2 * rfx, Q2y = vv2 * b2 * rfy, Q2z = z2.y;
        float Q3x = u3 * b3 * rfx, Q3y = vv3 * b3 * rfy, Q3z = z3.y;

        // Replicate reference's broadcast bug: point-p's z==0 masks COORDINATE p
        // of all three points (zmask evaluated on original values).
        bool zm0 = (Q1z == 0.0f), zm1 = (Q2z == 0.0f), zm2 = (Q3z == 0.0f);
        if (zm0) { Q1x = 1e-4f; Q2x = 1e-4f; Q3x = 1e-4f; }
        if (zm1) { Q1y = 1e-4f; Q2y = 1e-4f; Q3y = 1e-4f; }
        if (zm2) { Q1z = 1e-4f; Q2z = 1e-4f; Q3z = 1e-4f; }

        float ux = Q2x - Q1x, uy = Q2y - Q1y, uz = Q2z - Q1z;
        float wx = Q3x - Q1x, wy = Q3y - Q1y, wz = Q3z - Q1z;

        // cross products (no FMA contraction, to track the reference closely)
        float gnx = __fsub_rn(__fmul_rn(v0y, w1z), __fmul_rn(v0z, w1y));
        float gny = __fsub_rn(__fmul_rn(v0z, w1x), __fmul_rn(v0x, w1z));
        float gnz = __fsub_rn(__fmul_rn(v0x, w1y), __fmul_rn(v0y, w1x));
        float dnx = __fsub_rn(__fmul_rn(uy, wz), __fmul_rn(uz, wy));
        float dny = __fsub_rn(__fmul_rn(uz, wx), __fmul_rn(ux, wz));
        float dnz = __fsub_rn(__fmul_rn(ux, wy), __fmul_rn(uy, wx));

        float gnn = sqrtf(gnx*gnx + gny*gny + gnz*gnz);
        float dnn = sqrtf(dnx*dnx + dny*dny + dnz*dnz);
        if (gnn == 0.0f) gnn = 0.01f;
        if (dnn == 0.0f) dnn = 0.01f;
        float L = fabsf(gnx / gnn - dnx / dnn)
                + fabsf(gny / gnn - dny / dnn)
                + fabsf(gnz / gnn - dnz / dnn);

        unsigned int key = 0xFFFFFFFFu;
        if (maskf) {
            key = __float_as_uint(L);
            lsum += (double)L;
            lcnt++;
        }
        // warp-aggregated histogram atomic (cuts hot-bin contention)
        unsigned int act = __ballot_sync(0xFFFFFFFFu, maskf);
        if (maskf) {
            unsigned int bin = key >> 16;
            unsigned int peers = __match_any_sync(act, bin);
            int leader = __ffs(peers) - 1;
            if ((threadIdx.x & 31) == leader)
                atomicAdd(&g_hist_hi[bin], (unsigned int)__popc(peers));
        }
        g_keys[b * GN + g] = key;
    }

    // warp reduce -> one atomic per warp
    for (int off = 16; off; off >>= 1) {
        lsum += __shfl_down_sync(0xFFFFFFFFu, lsum, off);
        lcnt += __shfl_down_sync(0xFFFFFFFFu, lcnt, off);
    }
    if ((threadIdx.x & 31) == 0) {
        if (lsum != 0.0) atomicAdd(&g_total_sum, lsum);
        if (lcnt)        atomicAdd(&g_n, lcnt);
    }
}

// ---------------- K2: find hi-16 bucket containing rank drop = n/4 -------
__global__ void k_select_hi() {
    __shared__ unsigned int ps[1024];
    __shared__ unsigned int ex[1024];
    unsigned int t = threadIdx.x;
    unsigned int c = 0;
    #pragma unroll 8
    for (int i = 0; i < 64; i++) c += g_hist_hi[t * 64 + i];
    ps[t] = c;
    __syncthreads();
    if (t == 0) {
        unsigned int run = 0;
        for (int i = 0; i < 1024; i++) { ex[i] = run; run += ps[i]; }
    }
    __syncthreads();
    unsigned int drop = g_n >> 2;
    if (drop == 0) {
        if (t == 0) { g_bucket = 0u; g_rrem = 0u; }
        return;
    }
    if (ex[t] < drop && drop <= ex[t] + ps[t]) {
        unsigned int run = ex[t];
        for (int i = 0; i < 64; i++) {
            unsigned int cc = g_hist_hi[t * 64 + i];
            if (run + cc >= drop) { g_bucket = t * 64 + i; g_rrem = drop - run; break; }
            run += cc;
        }
    }
}

// ---------------- K3: sum below bucket + low-16 histogram of bucket ------
__global__ void k_refine() {
    int i = blockIdx.x * blockDim.x + threadIdx.x;
    double lsum = 0.0;
    unsigned int bucket = g_bucket;
    if (i < TOTAL) {
        unsigned int key = g_keys[i];
        if (key != 0xFFFFFFFFu) {
            unsigned int hi = key >> 16;
            if (hi < bucket) lsum = (double)__uint_as_float(key);
            else if (hi == bucket) atomicAdd(&g_hist_lo[key & 0xFFFFu], 1u);
        }
    }
    for (int off = 16; off; off >>= 1)
        lsum += __shfl_down_sync(0xFFFFFFFFu, lsum, off);
    if ((threadIdx.x & 31) == 0 && lsum != 0.0)
        atomicAdd(&g_sum_below, lsum);
}

// ---------------- K4: resolve exact threshold, write answer --------------
__global__ void k_final(float* __restrict__ out) {
    __shared__ unsigned int ps[1024];
    __shared__ double       ws[1024];
    __shared__ unsigned int ex[1024];
    __shared__ double       wex[1024];
    unsigned int t = threadIdx.x;
    unsigned int bucket = g_bucket;
    unsigned int r = g_rrem;
    unsigned int n = g_n;
    unsigned int drop = n >> 2;
    double total = g_total_sum;

    unsigned int c = 0; double w = 0.0;
    for (int i = 0; i < 64; i++) {
        unsigned int cc = g_hist_lo[t * 64 + i];
        c += cc;
        if (cc) w += (double)cc * (double)__uint_as_float((bucket << 16) | (t * 64 + i));
    }
    ps[t] = c; ws[t] = w;
    __syncthreads();
    if (t == 0) {
        unsigned int run = 0; double wr = 0.0;
        for (int i = 0; i < 1024; i++) { ex[i] = run; wex[i] = wr; run += ps[i]; wr += ws[i]; }
    }
    __syncthreads();

    if (r == 0) {   // drop == 0: nothing trimmed
        if (t == 0) {
            unsigned int keep = n - drop;
            out[0] = (float)(total / (double)(keep ? keep : 1u));
        }
        return;
    }
    if (ex[t] < r && r <= ex[t] + ps[t]) {
        unsigned int run = ex[t]; double wr = wex[t];
        for (int i = 0; i < 64; i++) {
            unsigned int cc = g_hist_lo[t * 64 + i];
            double v = (double)__uint_as_float((bucket << 16) | (t * 64 + i));
            if (run + cc >= r) {
                double dropped = g_sum_below + wr + (double)(r - run) * v;
                unsigned int keep = n - drop;
                out[0] = (float)((total - dropped) / (double)(keep ? keep : 1u));
                break;
            }
            run += cc;
            if (cc) wr += (double)cc * v;
        }
    }
}

// ---------------- launch -------------------------------------------------
extern "C" void kernel_launch(void* const* d_in, const int* in_sizes, int n_in,
                              void* d_out, int out_size) {
    const float* gt  = (const float*)d_in[0];
    const float* pr  = (const float*)d_in[1];
    const int*   p1x = (const int*)d_in[2];
    const int*   p1y = (const int*)d_in[3];
    const int*   p2x = (const int*)d_in[4];
    const int*   p2y = (const int*)d_in[5];
    const int*   p3x = (const int*)d_in[6];
    const int*   p3y = (const int*)d_in[7];
    float* out = (float*)d_out;

    k_zero<<<256, 256>>>();
    k_zip<<<(NPIX / 4 + 255) / 256, 256>>>(gt, pr);
    k_main<<<(GN + 255) / 256, 256>>>(p1x, p1y, p2x, p2y, p3x, p3y);
    k_select_hi<<<1, 1024>>>();
    k_refine<<<(TOTAL + 255) / 256, 256>>>();
    k_final<<<1, 1024>>>(out);
}